// round 15
// baseline (speedup 1.0000x reference)
#include <cuda_runtime.h>
#include <math.h>

// Shapes (fixed): B=4, N=1024, D=INNER=1024, H=16, DH=64, SCALE=0.125
// World (7-round elimination): inputs f32, in_sizes = element counts
// {4194304x2, 1048576x4, 1024x2}; out_size==4194304 f32 elements => the
// output is the REAL PART of the complex result ([4,1024,1024] float32,
// 16MB). Every final write below is guarded by out_size.

#define TM 64
#define TN 64
#define TK 16

// -------- scratch (static device globals; exonerated R8/R11) ---------------
__device__ float  g_w_re[4194304];      // 16 MB : qkv projection [B*N,H*DH]
__device__ float  g_w_im[4194304];
__device__ float  g_o_re[4194304];      // 16 MB : attention output
__device__ float  g_o_im[4194304];
__device__ float2 g_dots[67108864];     // 512 MB: [B,H,N,N] scores/attn

// ---------------------------------------------------------------------------
// Complex GEMM "NT": C = scale * A[M,K] (x) B[N,K]^T (+conj/+bias), batched.
// FINAL=false: writes split re/im (scratch) or interleaved float2 (ILV).
// FINAL=true : writes guarded output - real-only f32 (pairs=0) or f32 pairs.
// 64x64x16 tiles, 256 threads, 4x4 complex micro-tile, float4 loaders.
// ---------------------------------------------------------------------------
template<bool CONJB, bool ILV, bool BIAS, bool FINAL>
__global__ void __launch_bounds__(256)
cgemm_nt(int K,
         const float* __restrict__ Are, const float* __restrict__ Aim,
         long long sbA, long long shA,
         const float* __restrict__ Bre, const float* __restrict__ Bim,
         long long sbB, long long shB,
         float* __restrict__ Cre, float* __restrict__ Cim,
         float2* __restrict__ Cilv, long long sbC, long long shC,
         float scale,
         const float* __restrict__ bre, const float* __restrict__ bim,
         float* __restrict__ fout, long long out_n, int pairs)
{
    __shared__ float As_re[TK][TM + 4], As_im[TK][TM + 4];
    __shared__ float Bs_re[TK][TN + 4], Bs_im[TK][TN + 4];

    const int z = blockIdx.z;
    const long long zb = z >> 4, zh = z & 15;
    const long long offA = zb * sbA + zh * shA;
    const long long offB = zb * sbB + zh * shB;
    const long long offC = zb * sbC + zh * shC;

    const int m0 = blockIdx.x * TM;
    const int n0 = blockIdx.y * TN;

    const int tid = threadIdx.x;
    const int lk4 = tid & 3;        // k-group of 4 (float4)
    const int lr  = tid >> 2;       // row 0..63
    const int tx  = tid & 15, ty = tid >> 4;

    float cr[4][4] = {}, ci[4][4] = {};

    for (int k0 = 0; k0 < K; k0 += TK) {
        {
            const long long ra = offA + (long long)(m0 + lr) * 1024 + k0 + lk4 * 4;
            const long long rb = offB + (long long)(n0 + lr) * 1024 + k0 + lk4 * 4;
            float4 ar = *(const float4*)&Are[ra];
            float4 ai = *(const float4*)&Aim[ra];
            float4 br = *(const float4*)&Bre[rb];
            float4 bi = *(const float4*)&Bim[rb];
            As_re[lk4*4+0][lr] = ar.x; As_re[lk4*4+1][lr] = ar.y;
            As_re[lk4*4+2][lr] = ar.z; As_re[lk4*4+3][lr] = ar.w;
            As_im[lk4*4+0][lr] = ai.x; As_im[lk4*4+1][lr] = ai.y;
            As_im[lk4*4+2][lr] = ai.z; As_im[lk4*4+3][lr] = ai.w;
            Bs_re[lk4*4+0][lr] = br.x; Bs_re[lk4*4+1][lr] = br.y;
            Bs_re[lk4*4+2][lr] = br.z; Bs_re[lk4*4+3][lr] = br.w;
            Bs_im[lk4*4+0][lr] = bi.x; Bs_im[lk4*4+1][lr] = bi.y;
            Bs_im[lk4*4+2][lr] = bi.z; Bs_im[lk4*4+3][lr] = bi.w;
        }
        __syncthreads();
        #pragma unroll
        for (int k = 0; k < TK; k++) {
            float4 arv = *(const float4*)&As_re[k][ty * 4];
            float4 aiv = *(const float4*)&As_im[k][ty * 4];
            float4 brv = *(const float4*)&Bs_re[k][tx * 4];
            float4 biv = *(const float4*)&Bs_im[k][tx * 4];
            float arr[4] = {arv.x, arv.y, arv.z, arv.w};
            float aii[4] = {aiv.x, aiv.y, aiv.z, aiv.w};
            float brr[4] = {brv.x, brv.y, brv.z, brv.w};
            float bii[4] = {biv.x, biv.y, biv.z, biv.w};
            #pragma unroll
            for (int i = 0; i < 4; i++)
                #pragma unroll
                for (int j = 0; j < 4; j++) {
                    if (CONJB) {
                        cr[i][j] += arr[i] * brr[j] + aii[i] * bii[j];
                        ci[i][j] += aii[i] * brr[j] - arr[i] * bii[j];
                    } else {
                        cr[i][j] += arr[i] * brr[j] - aii[i] * bii[j];
                        ci[i][j] += arr[i] * bii[j] + aii[i] * brr[j];
                    }
                }
        }
        __syncthreads();
    }

    #pragma unroll
    for (int i = 0; i < 4; i++) {
        int m = m0 + ty * 4 + i;
        #pragma unroll
        for (int j = 0; j < 4; j++) {
            int n = n0 + tx * 4 + j;
            float re = cr[i][j] * scale;
            float im = ci[i][j] * scale;
            if (BIAS) { re += bre[n]; im += bim[n]; }
            long long o = offC + (long long)m * 1024 + n;
            if (FINAL) {
                if (pairs) {                       // f32 interleaved pairs
                    if (2 * o + 1 < out_n) {
                        fout[2 * o]     = re;
                        fout[2 * o + 1] = im;
                    }
                } else {                           // real part only
                    if (o < out_n) fout[o] = re;
                }
            } else if (ILV) {
                Cilv[o] = make_float2(re, im);
            } else {
                Cre[o] = re;
                Cim[o] = im;
            }
        }
    }
}

// ---------------------------------------------------------------------------
// AV GEMM "NN": O[q,d] = sum_m attn[q,m] * w[m,d], per (b,h). K=1024, N=64.
// ---------------------------------------------------------------------------
__global__ void __launch_bounds__(256)
cgemm_nn_attn(const float2* __restrict__ Ailv,
              const float* __restrict__ Bre, const float* __restrict__ Bim,
              float* __restrict__ Cre, float* __restrict__ Cim)
{
    __shared__ float As_re[TK][TM + 4], As_im[TK][TM + 4];
    __shared__ float Bs_re[TK][TN + 4], Bs_im[TK][TN + 4];

    const int z = blockIdx.z;
    const long long b = z >> 4, h = z & 15;
    const long long offA  = (long long)z << 20;           // z * 1024*1024
    const long long offBC = (b << 20) + h * 64;
    const int m0 = blockIdx.x * TM;

    const int tid = threadIdx.x;
    const int lk = tid & 15, lr = tid >> 4;
    const int ln = tid & 63, lkb = tid >> 6;
    const int tx = tid & 15, ty = tid >> 4;

    float cr[4][4] = {}, ci[4][4] = {};

    for (int k0 = 0; k0 < 1024; k0 += TK) {
        #pragma unroll
        for (int i = 0; i < 4; i++) {
            int r = lr + i * 16;
            float2 v = Ailv[offA + (long long)(m0 + r) * 1024 + k0 + lk];
            As_re[lk][r] = v.x;
            As_im[lk][r] = v.y;
        }
        #pragma unroll
        for (int i = 0; i < 4; i++) {
            int k = lkb + i * 4;
            Bs_re[k][ln] = Bre[offBC + (long long)(k0 + k) * 1024 + ln];
            Bs_im[k][ln] = Bim[offBC + (long long)(k0 + k) * 1024 + ln];
        }
        __syncthreads();
        #pragma unroll
        for (int k = 0; k < TK; k++) {
            float4 arv = *(const float4*)&As_re[k][ty * 4];
            float4 aiv = *(const float4*)&As_im[k][ty * 4];
            float4 brv = *(const float4*)&Bs_re[k][tx * 4];
            float4 biv = *(const float4*)&Bs_im[k][tx * 4];
            float arr[4] = {arv.x, arv.y, arv.z, arv.w};
            float aii[4] = {aiv.x, aiv.y, aiv.z, aiv.w};
            float brr[4] = {brv.x, brv.y, brv.z, brv.w};
            float bii[4] = {biv.x, biv.y, biv.z, biv.w};
            #pragma unroll
            for (int i = 0; i < 4; i++)
                #pragma unroll
                for (int j = 0; j < 4; j++) {
                    cr[i][j] += arr[i] * brr[j] - aii[i] * bii[j];
                    ci[i][j] += arr[i] * bii[j] + aii[i] * brr[j];
                }
        }
        __syncthreads();
    }

    #pragma unroll
    for (int i = 0; i < 4; i++) {
        int m = m0 + ty * 4 + i;
        #pragma unroll
        for (int j = 0; j < 4; j++) {
            int n = tx * 4 + j;
            Cre[offBC + (long long)m * 1024 + n] = cr[i][j];
            Cim[offBC + (long long)m * 1024 + n] = ci[i][j];
        }
    }
}

// ---------------------------------------------------------------------------
// attn = softmax(|dots|) * dots/|dots|, in place. One block per row of 1024.
// ---------------------------------------------------------------------------
__global__ void __launch_bounds__(256)
softmax_polar(float2* __restrict__ dots)
{
    const long long base = (long long)blockIdx.x << 10;
    const int t = threadIdx.x;

    float2 zv[4];
    float  mg[4];
    float  mx = -3.4e38f;
    #pragma unroll
    for (int i = 0; i < 4; i++) {
        zv[i] = dots[base + t + (i << 8)];
        mg[i] = sqrtf(zv[i].x * zv[i].x + zv[i].y * zv[i].y);
        mx = fmaxf(mx, mg[i]);
    }

    __shared__ float red1[8];
    __shared__ float red2[8];
    #pragma unroll
    for (int o = 16; o; o >>= 1) mx = fmaxf(mx, __shfl_xor_sync(0xffffffffu, mx, o));
    if ((t & 31) == 0) red1[t >> 5] = mx;
    __syncthreads();
    mx = red1[0];
    #pragma unroll
    for (int i = 1; i < 8; i++) mx = fmaxf(mx, red1[i]);

    float p[4], s = 0.f;
    #pragma unroll
    for (int i = 0; i < 4; i++) { p[i] = __expf(mg[i] - mx); s += p[i]; }
    #pragma unroll
    for (int o = 16; o; o >>= 1) s += __shfl_xor_sync(0xffffffffu, s, o);
    if ((t & 31) == 0) red2[t >> 5] = s;
    __syncthreads();
    s = 0.f;
    #pragma unroll
    for (int i = 0; i < 8; i++) s += red2[i];
    const float inv = 1.f / s;

    #pragma unroll
    for (int i = 0; i < 4; i++) {
        float a = p[i] * inv;
        float2 o;
        if (mg[i] > 0.f) {
            float f = a / mg[i];
            o = make_float2(zv[i].x * f, zv[i].y * f);
        } else {
            o = make_float2(a, 0.f);
        }
        dots[base + t + (i << 8)] = o;
    }
}

// ---------------------------------------------------------------------------
extern "C" void kernel_launch(void* const* d_in, const int* in_sizes, int n_in,
                              void* d_out, int out_size)
{
    // size-class mapper (PROVEN to match); in-class order = reference order
    const float* xs[2] = {nullptr, nullptr};
    const float* ws[4] = {nullptr, nullptr, nullptr, nullptr};
    const float* bs[2] = {nullptr, nullptr};
    int nx = 0, nw = 0, nb = 0;
    for (int i = 0; i < n_in; i++) {
        if (in_sizes[i] == 4194304)      { if (nx < 2) xs[nx++] = (const float*)d_in[i]; }
        else if (in_sizes[i] == 1048576) { if (nw < 4) ws[nw++] = (const float*)d_in[i]; }
        else if (in_sizes[i] == 1024)    { if (nb < 2) bs[nb++] = (const float*)d_in[i]; }
    }
    if (nx != 2 || nw != 4 || nb != 2) return;   // clean failure, never OOB

    // out_size==4194304 (proven in play) => real-part f32, 16MB writes.
    // out_size>=8388608 => interleaved re/im f32 pairs. Both hard-guarded.
    int pairs = (out_size >= 8388608) ? 1 : 0;

    float  *w_re, *w_im, *o_re, *o_im;
    float2 *dots;
    cudaGetSymbolAddress((void**)&w_re, g_w_re);
    cudaGetSymbolAddress((void**)&w_im, g_w_im);
    cudaGetSymbolAddress((void**)&o_re, g_o_re);
    cudaGetSymbolAddress((void**)&o_im, g_o_im);
    cudaGetSymbolAddress((void**)&dots, g_dots);

    dim3 blk(256);

    // 1) w = x @ Wqkv^T
    cgemm_nt<false, false, false, false><<<dim3(64, 16, 1), blk>>>(
        1024, xs[0], xs[1], 0LL, 0LL, ws[0], ws[1], 0LL, 0LL,
        w_re, w_im, nullptr, 0LL, 0LL, 1.0f, nullptr, nullptr,
        nullptr, 0LL, 0);

    // 2) dots = SCALE * w @ conj(w)^T per (b,h)
    cgemm_nt<true, true, false, false><<<dim3(16, 16, 64), blk>>>(
        64, w_re, w_im, 1048576LL, 64LL, w_re, w_im, 1048576LL, 64LL,
        nullptr, nullptr, dots, 16777216LL, 1048576LL, 0.125f,
        nullptr, nullptr, nullptr, 0LL, 0);

    // 3) attn = softmax(|dots|)*phase (in place)
    softmax_polar<<<65536, 256>>>(dots);

    // 4) o = attn @ w per (b,h)
    cgemm_nn_attn<<<dim3(16, 1, 64), blk>>>(dots, w_re, w_im, o_re, o_im);

    // 5) out = o @ Wout^T + bout -> guarded f32 (real-only or pairs)
    cgemm_nt<false, false, true, true><<<dim3(64, 16, 1), blk>>>(
        1024, o_re, o_im, 0LL, 0LL, ws[2], ws[3], 0LL, 0LL,
        nullptr, nullptr, nullptr, 0LL, 0LL, 1.0f, bs[0], bs[1],
        (float*)d_out, (long long)out_size, pairs);
}

// round 17
// speedup vs baseline: 1.2993x; 1.2993x over previous
#include <cuda_runtime.h>
#include <math.h>
#include <stdint.h>

// Shapes: B=4, N=1024, D=INNER=1024, H=16, DH=64, SCALE=0.125
// World (proven R15): f32 inputs, element-count sizes {4194304x2,1048576x4,1024x2},
// out_size==4194304 => output = REAL PART f32 [4,1024,1024], guarded writes.
// R16 lesson: ptxas targets sm_103 (no 'a') => tcgen05 unavailable; use legacy
// mma.sync tf32 (sm_80+, not arch-suffix-gated) for the tensor pipe.

#define TM 64
#define TN 64
#define TK 16

// -------- scratch ----------------------------------------------------------
__device__ float  g_w_re[4194304];
__device__ float  g_w_im[4194304];
__device__ float  g_o_re[4194304];
__device__ float  g_o_im[4194304];
__device__ float2 g_dots[67108864];

// ===================== tf32 mma.sync helpers ================================
__device__ __forceinline__ uint32_t f2tf(float f) {
    uint32_t r;
    asm("cvt.rna.tf32.f32 %0, %1;" : "=r"(r) : "f"(f));
    return r;
}
#define MMA8(c, a, b) \
    asm volatile("mma.sync.aligned.m16n8k8.row.col.f32.tf32.tf32.f32 " \
        "{%0,%1,%2,%3}, {%4,%5,%6,%7}, {%8,%9}, {%0,%1,%2,%3};" \
        : "+f"((c)[0]), "+f"((c)[1]), "+f"((c)[2]), "+f"((c)[3]) \
        : "r"((a)[0]), "r"((a)[1]), "r"((a)[2]), "r"((a)[3]), \
          "r"((b)[0]), "r"((b)[1]))

#define PM 133   // k-major A smem pitch (128 + 5, scrambles banks)
#define PN 69    // k-major B smem pitch (64 + 5)

// ---------------------------------------------------------------------------
// mma_proj<FINAL>: complex NT GEMM C[4096,1024] = A[4096,1024] x B[1024,1024]^T
// via tf32 mma.sync. FINAL=0 -> g_w_re/im. FINAL=1 -> guarded f32 out + bias.
// CTA 256 thr = 8 warps (4m x 2n), CTA tile 128x64, warp tile 32x32, K-tile 16.
// ---------------------------------------------------------------------------
template<bool FINAL>
__global__ void __launch_bounds__(256)
mma_proj(const float* __restrict__ Are, const float* __restrict__ Aim,
         const float* __restrict__ Bre, const float* __restrict__ Bim,
         const float* __restrict__ bre, const float* __restrict__ bim,
         float* __restrict__ fout, long long out_n, int pairs)
{
    __shared__ float Asr[16 * PM], Asi[16 * PM];
    __shared__ float Bsr[16 * PN], Bsi[16 * PN];

    const int tid = threadIdx.x, lane = tid & 31, wid = tid >> 5;
    const int wm = wid & 3, wn = wid >> 2;          // warp grid 4 x 2
    const int m0 = blockIdx.x * 128, n0 = blockIdx.y * 64;
    const int g = lane >> 2, tc = lane & 3;

    float cre[2][4][4] = {}, cim[2][4][4] = {};     // [mt][nt][frag]

    for (int kb = 0; kb < 1024; kb += 16) {
        // ---- load A 128x16 (2 float4/thread/array), k-major smem ----
        #pragma unroll
        for (int it = 0; it < 2; it++) {
            int idx = tid + it * 256;               // 0..511
            int row = idx >> 2, kq = idx & 3;
            long long ga = (long long)(m0 + row) * 1024 + kb + kq * 4;
            float4 vr = *(const float4*)&Are[ga];
            float4 vi = *(const float4*)&Aim[ga];
            Asr[(kq*4+0)*PM + row] = vr.x; Asr[(kq*4+1)*PM + row] = vr.y;
            Asr[(kq*4+2)*PM + row] = vr.z; Asr[(kq*4+3)*PM + row] = vr.w;
            Asi[(kq*4+0)*PM + row] = vi.x; Asi[(kq*4+1)*PM + row] = vi.y;
            Asi[(kq*4+2)*PM + row] = vi.z; Asi[(kq*4+3)*PM + row] = vi.w;
        }
        // ---- load B 64x16 (1 float4/thread/array) ----
        {
            int row = tid >> 2, kq = tid & 3;
            long long gb = (long long)(n0 + row) * 1024 + kb + kq * 4;
            float4 vr = *(const float4*)&Bre[gb];
            float4 vi = *(const float4*)&Bim[gb];
            Bsr[(kq*4+0)*PN + row] = vr.x; Bsr[(kq*4+1)*PN + row] = vr.y;
            Bsr[(kq*4+2)*PN + row] = vr.z; Bsr[(kq*4+3)*PN + row] = vr.w;
            Bsi[(kq*4+0)*PN + row] = vi.x; Bsi[(kq*4+1)*PN + row] = vi.y;
            Bsi[(kq*4+2)*PN + row] = vi.z; Bsi[(kq*4+3)*PN + row] = vi.w;
        }
        __syncthreads();

        #pragma unroll
        for (int ks = 0; ks < 2; ks++) {
            const int kk = ks * 8;
            // A fragments (row-major m16k8): a0:(g,tc) a1:(g+8,tc) a2:(g,tc+4) a3:(g+8,tc+4)
            uint32_t ar[2][4], ai[2][4], an[2][4];
            #pragma unroll
            for (int mt = 0; mt < 2; mt++) {
                int rm = wm * 32 + mt * 16 + g;
                ar[mt][0] = f2tf(Asr[(kk+tc  )*PM + rm]);
                ar[mt][1] = f2tf(Asr[(kk+tc  )*PM + rm + 8]);
                ar[mt][2] = f2tf(Asr[(kk+tc+4)*PM + rm]);
                ar[mt][3] = f2tf(Asr[(kk+tc+4)*PM + rm + 8]);
                ai[mt][0] = f2tf(Asi[(kk+tc  )*PM + rm]);
                ai[mt][1] = f2tf(Asi[(kk+tc  )*PM + rm + 8]);
                ai[mt][2] = f2tf(Asi[(kk+tc+4)*PM + rm]);
                ai[mt][3] = f2tf(Asi[(kk+tc+4)*PM + rm + 8]);
                #pragma unroll
                for (int q = 0; q < 4; q++) an[mt][q] = ai[mt][q] ^ 0x80000000u;
            }
            // B fragments (col-major k8n8): b0:(tc,g) b1:(tc+4,g)
            uint32_t br[4][2], bi[4][2];
            #pragma unroll
            for (int nt = 0; nt < 4; nt++) {
                int cn = wn * 32 + nt * 8 + g;
                br[nt][0] = f2tf(Bsr[(kk+tc  )*PN + cn]);
                br[nt][1] = f2tf(Bsr[(kk+tc+4)*PN + cn]);
                bi[nt][0] = f2tf(Bsi[(kk+tc  )*PN + cn]);
                bi[nt][1] = f2tf(Bsi[(kk+tc+4)*PN + cn]);
            }
            #pragma unroll
            for (int mt = 0; mt < 2; mt++)
                #pragma unroll
                for (int nt = 0; nt < 4; nt++) {
                    MMA8(cre[mt][nt], ar[mt], br[nt]);   // += Ar*Br
                    MMA8(cre[mt][nt], an[mt], bi[nt]);   // += (-Ai)*Bi
                    MMA8(cim[mt][nt], ar[mt], bi[nt]);   // += Ar*Bi
                    MMA8(cim[mt][nt], ai[mt], br[nt]);   // += Ai*Br
                }
        }
        __syncthreads();
    }

    // ---- epilogue: c[q]: q0:(g, c) q1:(g, c+1) q2:(g+8, c) q3:(g+8, c+1) ----
    #pragma unroll
    for (int mt = 0; mt < 2; mt++) {
        int rbase = m0 + wm * 32 + mt * 16;
        #pragma unroll
        for (int nt = 0; nt < 4; nt++) {
            int cbase = n0 + wn * 32 + nt * 8 + tc * 2;
            #pragma unroll
            for (int q = 0; q < 4; q++) {
                int m = rbase + g + (q >> 1) * 8;
                int n = cbase + (q & 1);
                float re = cre[mt][nt][q];
                float im = cim[mt][nt][q];
                long long o = (long long)m * 1024 + n;
                if (FINAL) {
                    re += bre[n];
                    im += bim[n];
                    if (pairs) {
                        if (2 * o + 1 < out_n) {
                            fout[2 * o]     = re;
                            fout[2 * o + 1] = im;
                        }
                    } else {
                        if (o < out_n) fout[o] = re;
                    }
                } else {
                    g_w_re[o] = re;
                    g_w_im[o] = im;
                }
            }
        }
    }
}

// ================= stages 2-4: UNCHANGED from passing R15 ==================
template<bool CONJB, bool ILV>
__global__ void __launch_bounds__(256)
cgemm_nt(int K,
         const float* __restrict__ Are, const float* __restrict__ Aim,
         long long sbA, long long shA,
         const float* __restrict__ Bre, const float* __restrict__ Bim,
         long long sbB, long long shB,
         float* __restrict__ Cre, float* __restrict__ Cim,
         float2* __restrict__ Cilv, long long sbC, long long shC,
         float scale)
{
    __shared__ float As_re[TK][TM + 4], As_im[TK][TM + 4];
    __shared__ float Bs_re[TK][TN + 4], Bs_im[TK][TN + 4];

    const int z = blockIdx.z;
    const long long zb = z >> 4, zh = z & 15;
    const long long offA = zb * sbA + zh * shA;
    const long long offB = zb * sbB + zh * shB;
    const long long offC = zb * sbC + zh * shC;

    const int m0 = blockIdx.x * TM;
    const int n0 = blockIdx.y * TN;

    const int tid = threadIdx.x;
    const int lk4 = tid & 3;
    const int lr  = tid >> 2;
    const int tx  = tid & 15, ty = tid >> 4;

    float cr[4][4] = {}, ci[4][4] = {};

    for (int k0 = 0; k0 < K; k0 += TK) {
        {
            const long long ra = offA + (long long)(m0 + lr) * 1024 + k0 + lk4 * 4;
            const long long rb = offB + (long long)(n0 + lr) * 1024 + k0 + lk4 * 4;
            float4 ar = *(const float4*)&Are[ra];
            float4 ai = *(const float4*)&Aim[ra];
            float4 br = *(const float4*)&Bre[rb];
            float4 bi = *(const float4*)&Bim[rb];
            As_re[lk4*4+0][lr] = ar.x; As_re[lk4*4+1][lr] = ar.y;
            As_re[lk4*4+2][lr] = ar.z; As_re[lk4*4+3][lr] = ar.w;
            As_im[lk4*4+0][lr] = ai.x; As_im[lk4*4+1][lr] = ai.y;
            As_im[lk4*4+2][lr] = ai.z; As_im[lk4*4+3][lr] = ai.w;
            Bs_re[lk4*4+0][lr] = br.x; Bs_re[lk4*4+1][lr] = br.y;
            Bs_re[lk4*4+2][lr] = br.z; Bs_re[lk4*4+3][lr] = br.w;
            Bs_im[lk4*4+0][lr] = bi.x; Bs_im[lk4*4+1][lr] = bi.y;
            Bs_im[lk4*4+2][lr] = bi.z; Bs_im[lk4*4+3][lr] = bi.w;
        }
        __syncthreads();
        #pragma unroll
        for (int k = 0; k < TK; k++) {
            float4 arv = *(const float4*)&As_re[k][ty * 4];
            float4 aiv = *(const float4*)&As_im[k][ty * 4];
            float4 brv = *(const float4*)&Bs_re[k][tx * 4];
            float4 biv = *(const float4*)&Bs_im[k][tx * 4];
            float arr[4] = {arv.x, arv.y, arv.z, arv.w};
            float aii[4] = {aiv.x, aiv.y, aiv.z, aiv.w};
            float brr[4] = {brv.x, brv.y, brv.z, brv.w};
            float bii[4] = {biv.x, biv.y, biv.z, biv.w};
            #pragma unroll
            for (int i = 0; i < 4; i++)
                #pragma unroll
                for (int j = 0; j < 4; j++) {
                    if (CONJB) {
                        cr[i][j] += arr[i] * brr[j] + aii[i] * bii[j];
                        ci[i][j] += aii[i] * brr[j] - arr[i] * bii[j];
                    } else {
                        cr[i][j] += arr[i] * brr[j] - aii[i] * bii[j];
                        ci[i][j] += arr[i] * bii[j] + aii[i] * brr[j];
                    }
                }
        }
        __syncthreads();
    }

    #pragma unroll
    for (int i = 0; i < 4; i++) {
        int m = m0 + ty * 4 + i;
        #pragma unroll
        for (int j = 0; j < 4; j++) {
            int n = n0 + tx * 4 + j;
            float re = cr[i][j] * scale;
            float im = ci[i][j] * scale;
            long long o = offC + (long long)m * 1024 + n;
            if (ILV) Cilv[o] = make_float2(re, im);
            else     { Cre[o] = re; Cim[o] = im; }
        }
    }
}

__global__ void __launch_bounds__(256)
cgemm_nn_attn(const float2* __restrict__ Ailv,
              const float* __restrict__ Bre, const float* __restrict__ Bim,
              float* __restrict__ Cre, float* __restrict__ Cim)
{
    __shared__ float As_re[TK][TM + 4], As_im[TK][TM + 4];
    __shared__ float Bs_re[TK][TN + 4], Bs_im[TK][TN + 4];

    const int z = blockIdx.z;
    const long long b = z >> 4, h = z & 15;
    const long long offA  = (long long)z << 20;
    const long long offBC = (b << 20) + h * 64;
    const int m0 = blockIdx.x * TM;

    const int tid = threadIdx.x;
    const int lk = tid & 15, lr = tid >> 4;
    const int ln = tid & 63, lkb = tid >> 6;
    const int tx = tid & 15, ty = tid >> 4;

    float cr[4][4] = {}, ci[4][4] = {};

    for (int k0 = 0; k0 < 1024; k0 += TK) {
        #pragma unroll
        for (int i = 0; i < 4; i++) {
            int r = lr + i * 16;
            float2 v = Ailv[offA + (long long)(m0 + r) * 1024 + k0 + lk];
            As_re[lk][r] = v.x;
            As_im[lk][r] = v.y;
        }
        #pragma unroll
        for (int i = 0; i < 4; i++) {
            int k = lkb + i * 4;
            Bs_re[k][ln] = Bre[offBC + (long long)(k0 + k) * 1024 + ln];
            Bs_im[k][ln] = Bim[offBC + (long long)(k0 + k) * 1024 + ln];
        }
        __syncthreads();
        #pragma unroll
        for (int k = 0; k < TK; k++) {
            float4 arv = *(const float4*)&As_re[k][ty * 4];
            float4 aiv = *(const float4*)&As_im[k][ty * 4];
            float4 brv = *(const float4*)&Bs_re[k][tx * 4];
            float4 biv = *(const float4*)&Bs_im[k][tx * 4];
            float arr[4] = {arv.x, arv.y, arv.z, arv.w};
            float aii[4] = {aiv.x, aiv.y, aiv.z, aiv.w};
            float brr[4] = {brv.x, brv.y, brv.z, brv.w};
            float bii[4] = {biv.x, biv.y, biv.z, biv.w};
            #pragma unroll
            for (int i = 0; i < 4; i++)
                #pragma unroll
                for (int j = 0; j < 4; j++) {
                    cr[i][j] += arr[i] * brr[j] - aii[i] * bii[j];
                    ci[i][j] += arr[i] * bii[j] + aii[i] * brr[j];
                }
        }
        __syncthreads();
    }

    #pragma unroll
    for (int i = 0; i < 4; i++) {
        int m = m0 + ty * 4 + i;
        #pragma unroll
        for (int j = 0; j < 4; j++) {
            int n = tx * 4 + j;
            Cre[offBC + (long long)m * 1024 + n] = cr[i][j];
            Cim[offBC + (long long)m * 1024 + n] = ci[i][j];
        }
    }
}

__global__ void __launch_bounds__(256)
softmax_polar(float2* __restrict__ dots)
{
    const long long base = (long long)blockIdx.x << 10;
    const int t = threadIdx.x;

    float2 zv[4];
    float  mg[4];
    float  mx = -3.4e38f;
    #pragma unroll
    for (int i = 0; i < 4; i++) {
        zv[i] = dots[base + t + (i << 8)];
        mg[i] = sqrtf(zv[i].x * zv[i].x + zv[i].y * zv[i].y);
        mx = fmaxf(mx, mg[i]);
    }

    __shared__ float red1[8];
    __shared__ float red2[8];
    #pragma unroll
    for (int o = 16; o; o >>= 1) mx = fmaxf(mx, __shfl_xor_sync(0xffffffffu, mx, o));
    if ((t & 31) == 0) red1[t >> 5] = mx;
    __syncthreads();
    mx = red1[0];
    #pragma unroll
    for (int i = 1; i < 8; i++) mx = fmaxf(mx, red1[i]);

    float p[4], s = 0.f;
    #pragma unroll
    for (int i = 0; i < 4; i++) { p[i] = __expf(mg[i] - mx); s += p[i]; }
    #pragma unroll
    for (int o = 16; o; o >>= 1) s += __shfl_xor_sync(0xffffffffu, s, o);
    if ((t & 31) == 0) red2[t >> 5] = s;
    __syncthreads();
    s = 0.f;
    #pragma unroll
    for (int i = 0; i < 8; i++) s += red2[i];
    const float inv = 1.f / s;

    #pragma unroll
    for (int i = 0; i < 4; i++) {
        float a = p[i] * inv;
        float2 o;
        if (mg[i] > 0.f) {
            float f = a / mg[i];
            o = make_float2(zv[i].x * f, zv[i].y * f);
        } else {
            o = make_float2(a, 0.f);
        }
        dots[base + t + (i << 8)] = o;
    }
}

// ---------------------------------------------------------------------------
extern "C" void kernel_launch(void* const* d_in, const int* in_sizes, int n_in,
                              void* d_out, int out_size)
{
    const float* xs[2] = {nullptr, nullptr};
    const float* ws[4] = {nullptr, nullptr, nullptr, nullptr};
    const float* bs[2] = {nullptr, nullptr};
    int nx = 0, nw = 0, nb = 0;
    for (int i = 0; i < n_in; i++) {
        if (in_sizes[i] == 4194304)      { if (nx < 2) xs[nx++] = (const float*)d_in[i]; }
        else if (in_sizes[i] == 1048576) { if (nw < 4) ws[nw++] = (const float*)d_in[i]; }
        else if (in_sizes[i] == 1024)    { if (nb < 2) bs[nb++] = (const float*)d_in[i]; }
    }
    if (nx != 2 || nw != 4 || nb != 2) return;

    int pairs = (out_size >= 8388608) ? 1 : 0;

    float  *w_re, *w_im, *o_re, *o_im;
    float2 *dots;
    cudaGetSymbolAddress((void**)&w_re, g_w_re);
    cudaGetSymbolAddress((void**)&w_im, g_w_im);
    cudaGetSymbolAddress((void**)&o_re, g_o_re);
    cudaGetSymbolAddress((void**)&o_im, g_o_im);
    cudaGetSymbolAddress((void**)&dots, g_dots);

    dim3 blk(256);

    // 1) w = x @ Wqkv^T  (tf32 mma.sync)
    mma_proj<false><<<dim3(32, 16), blk>>>(
        xs[0], xs[1], ws[0], ws[1], nullptr, nullptr, nullptr, 0LL, 0);

    // 2) dots = SCALE * w @ conj(w)^T per (b,h)
    cgemm_nt<true, true><<<dim3(16, 16, 64), blk>>>(
        64, w_re, w_im, 1048576LL, 64LL, w_re, w_im, 1048576LL, 64LL,
        nullptr, nullptr, dots, 16777216LL, 1048576LL, 0.125f);

    // 3) attn = softmax(|dots|)*phase (in place)
    softmax_polar<<<65536, 256>>>(dots);

    // 4) o = attn @ w per (b,h)
    cgemm_nn_attn<<<dim3(16, 1, 64), blk>>>(dots, w_re, w_im, o_re, o_im);

    // 5) out = o @ Wout^T + bout  (tf32 mma.sync, guarded output)
    mma_proj<true><<<dim3(32, 16), blk>>>(
        o_re, o_im, ws[2], ws[3], bs[0], bs[1],
        (float*)d_out, (long long)out_size, pairs);
}